// round 2
// baseline (speedup 1.0000x reference)
#include <cuda_runtime.h>

#define NN 50000
#define NE 600000
#define NR 500
#define NF 128
#define NH 4
#define EPB (NE / NN)   // 12 edges histogrammed per logits-block

typedef unsigned long long ull;

// ---------------- device scratch ----------------
__device__ float  g_cw[NH][NF];
__device__ float  g_ca[NH][NF];
__device__ float4 g_nl[NN];
__device__ float4 g_rl[NR];
__device__ int    g_deg[NN];
__device__ int    g_rowptr[NN + 1];
__device__ int    g_cursor[NN];
__device__ int2   g_edges[NE];
__device__ int    g_is64;
__device__ int    g_partials[256];

// ---------------- helpers ----------------
__device__ __forceinline__ ull pk2(float lo, float hi) {
    ull r; asm("mov.b64 %0, {%1, %2};" : "=l"(r) : "f"(lo), "f"(hi)); return r;
}
__device__ __forceinline__ float2 upk2(ull v) {
    float2 r; asm("mov.b64 {%0, %1}, %2;" : "=f"(r.x), "=f"(r.y) : "l"(v)); return r;
}
__device__ __forceinline__ ull ff2(ull a, ull b, ull c) {
    ull r; asm("fma.rn.f32x2 %0, %1, %2, %3;" : "=l"(r) : "l"(a), "l"(b), "l"(c)); return r;
}
__device__ __forceinline__ float edge_e(float x) {
    float l = x > 0.f ? x : 0.2f * x;
    return __expf(-l);
}

// ---------------- fused init: detect dtype + zero deg + cumW prep ----------------
__global__ void k_init(const int* __restrict__ A32, const float* __restrict__ w,
                       const float* __restrict__ a) {
    int i = blockIdx.x * 256 + threadIdx.x;
    if (i < NN) g_deg[i] = 0;
    if (blockIdx.x == 0 && threadIdx.x == 0) {
        // dst = arange(N): int64 => odd 32-bit words are 0
        int is64 = 1;
        for (int k = 1; k < 32; k += 2)
            if (A32[k] != 0) { is64 = 0; break; }
        g_is64 = is64;
    }
    if (blockIdx.x == 1 && threadIdx.x < NF) {
        int f = threadIdx.x;
        float c = 1.f;
#pragma unroll
        for (int h = 0; h < NH; h++) {
            if (h) c *= w[(h - 1) * NF + f];
            g_cw[h][f] = c;
            g_ca[h][f] = c * a[h * 2 * NF + f];
        }
    }
}

// block-of-128 4-way reduction
__device__ __forceinline__ void reduce4_store(float v0, float v1, float v2, float v3,
                                              float* dst4) {
    int f = threadIdx.x;
#pragma unroll
    for (int off = 16; off > 0; off >>= 1) {
        v0 += __shfl_down_sync(0xffffffffu, v0, off);
        v1 += __shfl_down_sync(0xffffffffu, v1, off);
        v2 += __shfl_down_sync(0xffffffffu, v2, off);
        v3 += __shfl_down_sync(0xffffffffu, v3, off);
    }
    __shared__ float sp[4][4];
    if ((f & 31) == 0) {
        int wg = f >> 5;
        sp[wg][0] = v0; sp[wg][1] = v1; sp[wg][2] = v2; sp[wg][3] = v3;
    }
    __syncthreads();
    if (f < 4) dst4[f] = sp[0][f] + sp[1][f] + sp[2][f] + sp[3][f];
    __syncthreads();   // allow reuse of sp by a second call
}

// ---------------- fused: node logits (+rel logits for first NR blocks) + deg ----------------
__global__ void k_logits(const float* __restrict__ h0, const float* __restrict__ inputr,
                         const float* __restrict__ a, const void* __restrict__ A) {
    int n = blockIdx.x, f = threadIdx.x;

    float hv = h0[n * NF + f];
    reduce4_store(hv * g_ca[0][f], hv * g_ca[1][f], hv * g_ca[2][f], hv * g_ca[3][f],
                  (float*)&g_nl[n]);

    if (n < NR) {
        float rv = inputr[n * NF + f];
        reduce4_store(rv * a[0 * 2 * NF + NF + f], rv * a[1 * 2 * NF + NF + f],
                      rv * a[2 * 2 * NF + NF + f], rv * a[3 * 2 * NF + NF + f],
                      (float*)&g_rl[n]);
    }

    // degree histogram: this block covers edges [n*EPB, n*EPB+EPB)
    if (f < EPB) {
        int e = n * EPB + f;
        int dst = g_is64 ? (int)((const long long*)A)[e] : ((const int*)A)[e];
        atomicAdd(&g_deg[dst], 1);
    }
}

// ---------------- 2-level exclusive scan ----------------
__global__ void k_scan1() {
    __shared__ int s[256];
    int tid = threadIdx.x;
    int i = blockIdx.x * 256 + tid;
    int v = (i < NN) ? g_deg[i] : 0;
    s[tid] = v;
    __syncthreads();
#pragma unroll
    for (int off = 1; off < 256; off <<= 1) {
        int t = (tid >= off) ? s[tid - off] : 0;
        __syncthreads();
        s[tid] += t;
        __syncthreads();
    }
    if (tid == 255) g_partials[blockIdx.x] = s[255];
    if (i < NN) g_rowptr[i] = s[tid] - v;
}

__global__ void k_scan2() {
    __shared__ int s[256];
    int tid = threadIdx.x;
    int nb = (NN + 255) / 256;
    int v = (tid < nb) ? g_partials[tid] : 0;
    s[tid] = v;
    __syncthreads();
#pragma unroll
    for (int off = 1; off < 256; off <<= 1) {
        int t = (tid >= off) ? s[tid - off] : 0;
        __syncthreads();
        s[tid] += t;
        __syncthreads();
    }
    g_partials[tid] = s[tid] - v;
}

__global__ void k_scan3() {
    int i = blockIdx.x * 256 + threadIdx.x;
    int off = g_partials[blockIdx.x];
    if (i < NN) {
        int r = g_rowptr[i] + off;
        g_rowptr[i] = r;
        g_cursor[i] = r;
    }
    if (blockIdx.x == 0 && threadIdx.x == 0) g_rowptr[NN] = NE;
}

__global__ void k_scatter(const void* __restrict__ A) {
    int e = blockIdx.x * blockDim.x + threadIdx.x;
    if (e >= NE) return;
    int dst, rel, src;
    if (g_is64) {
        const long long* a = (const long long*)A;
        dst = (int)a[e]; rel = (int)a[NE + e]; src = (int)a[2 * NE + e];
    } else {
        const int* a = (const int*)A;
        dst = a[e]; rel = a[NE + e]; src = a[2 * NE + e];
    }
    int pos = atomicAdd(&g_cursor[dst], 1);
    g_edges[pos] = make_int2(src, rel);
}

// ---------------- aggregation: 4 nodes (warps) per block ----------------
__global__ void __launch_bounds__(128) k_agg(const float4* __restrict__ h4,
                                             const float4* __restrict__ r4,
                                             float* __restrict__ out) {
    int wrp = threadIdx.x >> 5;
    int t   = threadIdx.x & 31;
    int n   = blockIdx.x * 4 + wrp;

    int beg = g_rowptr[n];
    int end = g_rowptr[n + 1];

    // per-head packed scale factors (constant per lane)
    ull cwA[NH], cwB[NH];
#pragma unroll
    for (int h = 0; h < NH; h++) {
        cwA[h] = pk2(g_cw[h][4 * t], g_cw[h][4 * t + 1]);
        cwB[h] = pk2(g_cw[h][4 * t + 2], g_cw[h][4 * t + 3]);
    }

    // acc_h = sum_e e_h * (cw_h (.) h0[src] - rel[r])   (2 packed pairs per head)
    ull aA0 = 0, aB0 = 0, aA1 = 0, aB1 = 0, aA2 = 0, aB2 = 0, aA3 = 0, aB3 = 0;
    float rs0 = 0.f, rs1 = 0.f, rs2 = 0.f, rs3 = 0.f;

    __shared__ float4 s_e[4][32];
    __shared__ int s_src[4][32];
    __shared__ int s_rel[4][32];

    for (int base = beg; base < end; base += 32) {
        int c = end - base;
        if (c > 32) c = 32;
        if (t < c) {
            int2 er = g_edges[base + t];
            float4 nl = g_nl[er.x];
            float4 rl = g_rl[er.y];
            float4 ev;
            ev.x = edge_e(nl.x + rl.x);
            ev.y = edge_e(nl.y + rl.y);
            ev.z = edge_e(nl.z + rl.z);
            ev.w = edge_e(nl.w + rl.w);
            s_e[wrp][t] = ev; s_src[wrp][t] = er.x; s_rel[wrp][t] = er.y;
        }
        __syncwarp();
#pragma unroll 2
        for (int j = 0; j < c; j++) {
            int src = s_src[wrp][j], rel = s_rel[wrp][j];
            float4 hv = h4[src * 32 + t];
            float4 rv = r4[rel * 32 + t];
            float4 ev = s_e[wrp][j];
            ull hA  = pk2(hv.x, hv.y),  hB  = pk2(hv.z, hv.w);
            ull nrA = pk2(-rv.x, -rv.y), nrB = pk2(-rv.z, -rv.w);
            ull e, mA, mB;
            e = pk2(ev.x, ev.x);
            mA = ff2(cwA[0], hA, nrA); mB = ff2(cwB[0], hB, nrB);
            aA0 = ff2(mA, e, aA0);     aB0 = ff2(mB, e, aB0);
            e = pk2(ev.y, ev.y);
            mA = ff2(cwA[1], hA, nrA); mB = ff2(cwB[1], hB, nrB);
            aA1 = ff2(mA, e, aA1);     aB1 = ff2(mB, e, aB1);
            e = pk2(ev.z, ev.z);
            mA = ff2(cwA[2], hA, nrA); mB = ff2(cwB[2], hB, nrB);
            aA2 = ff2(mA, e, aA2);     aB2 = ff2(mB, e, aB2);
            e = pk2(ev.w, ev.w);
            mA = ff2(cwA[3], hA, nrA); mB = ff2(cwB[3], hB, nrB);
            aA3 = ff2(mA, e, aA3);     aB3 = ff2(mB, e, aB3);
            rs0 += ev.x; rs1 += ev.y; rs2 += ev.z; rs3 += ev.w;
        }
        __syncwarp();
    }

    float i0 = 1.f / rs0, i1 = 1.f / rs1, i2 = 1.f / rs2, i3 = 1.f / rs3;
    float4* o4 = (float4*)out;
    float2 pA, pB;
    float4 o;

    pA = upk2(aA0); pB = upk2(aB0);
    o.x = pA.x * i0; o.y = pA.y * i0; o.z = pB.x * i0; o.w = pB.y * i0;
    o4[(0 * NN + n) * 32 + t] = o;
    pA = upk2(aA1); pB = upk2(aB1);
    o.x = pA.x * i1; o.y = pA.y * i1; o.z = pB.x * i1; o.w = pB.y * i1;
    o4[(1 * NN + n) * 32 + t] = o;
    pA = upk2(aA2); pB = upk2(aB2);
    o.x = pA.x * i2; o.y = pA.y * i2; o.z = pB.x * i2; o.w = pB.y * i2;
    o4[(2 * NN + n) * 32 + t] = o;
    pA = upk2(aA3); pB = upk2(aB3);
    o.x = pA.x * i3; o.y = pA.y * i3; o.z = pB.x * i3; o.w = pB.y * i3;
    o4[(3 * NN + n) * 32 + t] = o;
}

// ---------------- launch ----------------
extern "C" void kernel_launch(void* const* d_in, const int* in_sizes, int n_in,
                              void* d_out, int out_size) {
    const float* h0     = (const float*)d_in[0];
    const float* inputr = (const float*)d_in[1];
    const float* w      = (const float*)d_in[2];
    const float* a      = (const float*)d_in[3];
    const void*  A      = d_in[4];
    float* out = (float*)d_out;

    int nbN = (NN + 255) / 256;
    int nbE = (NE + 255) / 256;

    k_init<<<nbN, 256>>>((const int*)A, w, a);
    k_logits<<<NN, 128>>>(h0, inputr, a, A);
    k_scan1<<<nbN, 256>>>();
    k_scan2<<<1, 256>>>();
    k_scan3<<<nbN, 256>>>();
    k_scatter<<<nbE, 256>>>(A);
    k_agg<<<NN / 4, 128>>>((const float4*)h0, (const float4*)inputr, out);
}